// round 4
// baseline (speedup 1.0000x reference)
#include <cuda_runtime.h>

#define S    512
#define NA   180
#define NB   4
#define WS   48
#define QA   45            // angles per phase
#define PI_D 3.14159265358979323846

// filtered sinogram, batch-pair interleaved: [pair][a][s] = {e0, e1, d0, d1}
// e_b = w_b[s] + 0.5*d_b,  d_b = w_b[s+1] - w_b[s]
__device__ float4 g_xf4[2 * NA * S];

// ---------------------------------------------------------------------------
// Stage 1: ramp filter, register-sliding FIR (one block per (b,a), 64 thr).
// ---------------------------------------------------------------------------
#define OFFM(d) ((d) + ((1 + (d)) >> 3))
#define OFFP(d) ((d) + ((7 + (d)) >> 3))

__global__ void __launch_bounds__(64) filter_kernel(const float* __restrict__ x) {
    const int a = blockIdx.x % NA;
    const int b = blockIdx.x / NA;

    __shared__ float P[1736];
    __shared__ float sg[256];
    __shared__ float sw[S + 8];

    const int t = threadIdx.x;

    #pragma unroll
    for (int i = t; i < 512; i += 64) {
        P[i + (i >> 3)] = 0.0f;
        int j = i + 1024;
        P[j + (j >> 3)] = 0.0f;
    }
    #pragma unroll
    for (int i = t; i < S; i += 64) {
        int ii = i + 512;
        P[ii + (ii >> 3)] = x[(b * S + i) * NA + a];
    }
    #pragma unroll
    for (int i = t; i < 256; i += 64) {
        float dd = (float)(2 * i + 1);
        sg[i] = -2.0f / ((float)(PI_D * PI_D) * dd * dd);
    }
    __syncthreads();

    float acc[8];
    #pragma unroll
    for (int k = 0; k < 8; ++k)
        acc[k] = 0.5f * P[9 * t + 576 + k];

    float Am[16], Ap[16];
    int A0 = 9 * t + 1;
    int A1 = 9 * t + 1132;

    #pragma unroll
    for (int d0 = 0; d0 < 8; ++d0) {
        Am[d0] = P[A0 + OFFM(d0)];
        Ap[d0] = P[A1 + OFFP(16 + d0)];
    }

    #pragma unroll 1
    for (int g = 0; g < 32; ++g) {
        #pragma unroll
        for (int jj = 0; jj < 8; ++jj) {
            float gc = sg[255 - 8 * g - jj];
            #pragma unroll
            for (int k = 0; k < 8; ++k) {
                float av = Am[(2 * jj + k) & 15];
                float bv = Ap[(k - 2 * jj) & 15];
                acc[k] = fmaf(gc, av + bv, acc[k]);
            }
            Am[(2 * jj + 8) & 15]  = P[A0 + OFFM(2 * jj + 8)];
            Am[(2 * jj + 9) & 15]  = P[A0 + OFFM(2 * jj + 9)];
            Ap[(14 - 2 * jj) & 15] = P[A1 + OFFP(14 - 2 * jj)];
            Ap[(15 - 2 * jj) & 15] = P[A1 + OFFP(15 - 2 * jj)];
        }
        A0 += 18;
        A1 -= 18;
    }

    #pragma unroll
    for (int k = 0; k < 8; ++k)
        sw[8 * t + k] = acc[k];
    if (t == 0) sw[S] = 0.0f;
    __syncthreads();

    float4* o4 = &g_xf4[((b >> 1) * NA + a) * S];
    const int h = b & 1;
    #pragma unroll
    for (int k = 0; k < 8; ++k) {
        int s = 8 * t + k;
        float lo = sw[s];
        float d  = sw[s + 1] - lo;
        float* po = (float*)&o4[s];
        po[h]     = fmaf(0.5f, d, lo);
        po[2 + h] = d;
    }
}

// ---------------------------------------------------------------------------
// Stage 2: backprojection, batch-paired f32x2.
// Grid (16,16,2): 32x32 tile x one batch PAIR. 256 threads.
// Warp = 8x x 4y (small per-angle index span -> 2-wavefront LDS.128).
// 4 phases x 45 angles of float4 windows in smem.
// ---------------------------------------------------------------------------
__global__ void __launch_bounds__(256, 4) backproj_kernel(float* __restrict__ out) {
    __shared__ float4 win4[QA * WS];         // 34560 B
    __shared__ float4 consA[NA];             // {cs, cs, cz, cz}
    __shared__ float4 consB[NA];             // {ns, ns, 8ns, 8ns}
    __shared__ int    w0s[NA];

    const int tid  = threadIdx.x;
    const int pair = blockIdx.z;             // 0,1 -> batches (2p, 2p+1)
    const int x0   = blockIdx.x * 32;
    const int y0   = blockIdx.y * 32;

    const int lane = tid & 31;
    const int w    = tid >> 5;
    const int lx8  = lane & 7;
    const int x    = ((w & 3) << 3) + lx8;               // 0..31
    const int yb   = (lane >> 3) + ((w >> 2) << 2);      // 0..7 (slots +8k)

    const int b0 = 2 * pair, b1 = 2 * pair + 1;
    const float invh = 2.0f / 511.0f;

    // ---- early out: tile fully outside the unit circle ----
    {
        float ux0 = fmaf((float)x0,        invh, -1.0f);
        float ux1 = fmaf((float)(x0 + 31), invh, -1.0f);
        float uy0 = fmaf((float)y0,        invh, -1.0f);
        float uy1 = fmaf((float)(y0 + 31), invh, -1.0f);
        float mx = (ux0 <= 0.0f && ux1 >= 0.0f) ? 0.0f : fminf(fabsf(ux0), fabsf(ux1));
        float my = (uy0 <= 0.0f && uy1 >= 0.0f) ? 0.0f : fminf(fabsf(uy0), fabsf(uy1));
        if (mx * mx + my * my > 1.0f) {
            #pragma unroll
            for (int k = 0; k < 4; ++k) {
                int y = y0 + yb + 8 * k;
                out[(b0 * S + y) * S + x0 + x] = 0.0f;
                out[(b1 * S + y) * S + x0 + x] = 0.0f;
            }
            return;
        }
    }

    // ---- per-angle tables ----
    if (tid < NA) {
        float th = (float)tid * (float)(PI_D / 180.0);
        float sn, cs;
        sincosf(th, &sn, &cs);
        float pb = 255.5f + ((float)x0 - 255.5f) * cs - ((float)y0 - 255.5f) * sn;
        float pmin = pb + fminf(cs * 31.0f, 0.0f) + fminf(-sn * 31.0f, 0.0f);
        int w0 = (int)floorf(pmin) - 1;           // local p in [1, ~46)
        w0s[tid] = w0;
        float cz = pb - (float)w0 - 0.5f;
        float ns = -sn;
        consA[tid] = make_float4(cs, cs, cz, cz);
        consB[tid] = make_float4(ns, ns, 8.0f * ns, 8.0f * ns);
    }
    __syncthreads();

    // ---- packed per-thread constants ----
    unsigned long long FX2, FY2;
    {
        float fx = (float)x, fy = (float)yb;
        asm("mov.b64 %0, {%1, %1};" : "=l"(FX2) : "f"(fx));
        asm("mov.b64 %0, {%1, %1};" : "=l"(FY2) : "f"(fy));
    }
    const unsigned long long MAG2  = 0x4B0000004B000000ull;
    const unsigned long long NMAG2 = 0xCB000000CB000000ull;
    const unsigned long long NONE2 = 0xBF800000BF800000ull;

    const unsigned wbase0 = (unsigned)__cvta_generic_to_shared(win4) - 0xB0000000u;
    const unsigned cA0 = (unsigned)__cvta_generic_to_shared(consA);
    const unsigned cB0 = (unsigned)__cvta_generic_to_shared(consB);

    unsigned long long aE0 = 0, aF0 = 0, aE1 = 0, aF1 = 0;
    unsigned long long aE2 = 0, aF2 = 0, aE3 = 0, aF3 = 0;

    const float4* __restrict__ grow4 = &g_xf4[pair * NA * S];

    const int al = (tid < 240) ? tid / WS : 0;     // 0..4
    const int oo = tid - al * WS;

    #pragma unroll 1
    for (int phase = 0; phase < 4; ++phase) {
        const int abase = phase * QA;

        // ---- cooperative window fill (straight float4 copy) ----
        if (tid < 240) {
            #pragma unroll
            for (int ar = al; ar < QA; ar += 5) {
                int a  = abase + ar;
                int gi = w0s[a] + oo;
                float4 v;
                if ((unsigned)gi < (unsigned)S) {
                    v = grow4[a * S + gi];
                } else if (gi == -1) {
                    float4 v0 = grow4[a * S];
                    float w00 = v0.x - 0.5f * v0.z;
                    float w01 = v0.y - 0.5f * v0.w;
                    v = make_float4(0.5f * w00, 0.5f * w01, w00, w01);
                } else {
                    v = make_float4(0.0f, 0.0f, 0.0f, 0.0f);
                }
                win4[ar * WS + oo] = v;
            }
        }
        __syncthreads();

        // ---- accumulate 45 angles, 4 y-slots x 2 batches each ----
        unsigned caA = cA0 + (unsigned)abase * 16u;
        unsigned caB = cB0 + (unsigned)abase * 16u;
        unsigned wb  = wbase0;

        #pragma unroll 3
        for (int a = 0; a < QA; ++a) {
            asm volatile(
                "{\n\t"
                ".reg .b64 CS2, CZ2, NS2, NS8, BX2, P0, P1, P2, P3;\n\t"
                ".reg .b64 PM0, PM1, PM2, PM3, FL0, FL1, FL2, FL3;\n\t"
                ".reg .b64 Q0, Q1, Q2, Q3, E0, D0, E1, D1, E2, D2, E3, D3;\n\t"
                ".reg .b32 m0, m1, m2, m3, j0, j1, j2, j3;\n\t"
                "ld.shared.v2.b64 {CS2, CZ2}, [%8];\n\t"
                "ld.shared.v2.b64 {NS2, NS8}, [%9];\n\t"
                "fma.rn.f32x2 BX2, CS2, %10, CZ2;\n\t"
                "fma.rn.f32x2 P0, NS2, %11, BX2;\n\t"
                "add.rn.f32x2 P1, P0, NS8;\n\t"
                "add.rn.f32x2 P2, P1, NS8;\n\t"
                "add.rn.f32x2 P3, P2, NS8;\n\t"
                // slot 0
                "add.rn.f32x2 PM0, P0, %12;\n\t"
                "mov.b64 {m0, j0}, PM0;\n\t"
                "add.rn.f32x2 FL0, PM0, %13;\n\t"
                "fma.rn.f32x2 Q0, FL0, %14, P0;\n\t"
                "mad.lo.u32 m0, m0, 16, %15;\n\t"
                "ld.shared.v2.b64 {E0, D0}, [m0];\n\t"
                "add.rn.f32x2 %0, %0, E0;\n\t"
                "fma.rn.f32x2 %1, Q0, D0, %1;\n\t"
                // slot 1
                "add.rn.f32x2 PM1, P1, %12;\n\t"
                "mov.b64 {m1, j1}, PM1;\n\t"
                "add.rn.f32x2 FL1, PM1, %13;\n\t"
                "fma.rn.f32x2 Q1, FL1, %14, P1;\n\t"
                "mad.lo.u32 m1, m1, 16, %15;\n\t"
                "ld.shared.v2.b64 {E1, D1}, [m1];\n\t"
                "add.rn.f32x2 %2, %2, E1;\n\t"
                "fma.rn.f32x2 %3, Q1, D1, %3;\n\t"
                // slot 2
                "add.rn.f32x2 PM2, P2, %12;\n\t"
                "mov.b64 {m2, j2}, PM2;\n\t"
                "add.rn.f32x2 FL2, PM2, %13;\n\t"
                "fma.rn.f32x2 Q2, FL2, %14, P2;\n\t"
                "mad.lo.u32 m2, m2, 16, %15;\n\t"
                "ld.shared.v2.b64 {E2, D2}, [m2];\n\t"
                "add.rn.f32x2 %4, %4, E2;\n\t"
                "fma.rn.f32x2 %5, Q2, D2, %5;\n\t"
                // slot 3
                "add.rn.f32x2 PM3, P3, %12;\n\t"
                "mov.b64 {m3, j3}, PM3;\n\t"
                "add.rn.f32x2 FL3, PM3, %13;\n\t"
                "fma.rn.f32x2 Q3, FL3, %14, P3;\n\t"
                "mad.lo.u32 m3, m3, 16, %15;\n\t"
                "ld.shared.v2.b64 {E3, D3}, [m3];\n\t"
                "add.rn.f32x2 %6, %6, E3;\n\t"
                "fma.rn.f32x2 %7, Q3, D3, %7;\n\t"
                "}"
                : "+l"(aE0), "+l"(aF0), "+l"(aE1), "+l"(aF1),
                  "+l"(aE2), "+l"(aF2), "+l"(aE3), "+l"(aF3)
                : "r"(caA), "r"(caB), "l"(FX2), "l"(FY2),
                  "l"(MAG2), "l"(NMAG2), "l"(NONE2), "r"(wb));
            caA += 16u;
            caB += 16u;
            wb  += (unsigned)(WS * 16);
        }
        __syncthreads();
    }

    // ---- unpack, mask, scale, store (both batches) ----
    const float scale = (float)(PI_D / (2.0 * NA));
    const float ux  = fmaf((float)(x0 + x), invh, -1.0f);
    const float uxx = ux * ux;

#define STORE_SLOT(AE, AF, K)                                                 \
    {                                                                         \
        float e_lo, e_hi, f_lo, f_hi;                                         \
        asm("mov.b64 {%0, %1}, %2;" : "=f"(e_lo), "=f"(e_hi) : "l"(AE));      \
        asm("mov.b64 {%0, %1}, %2;" : "=f"(f_lo), "=f"(f_hi) : "l"(AF));      \
        int y = y0 + yb + 8 * (K);                                            \
        float uy = fmaf((float)y, invh, -1.0f);                               \
        bool in = (uxx + uy * uy <= 1.0f);                                    \
        out[(b0 * S + y) * S + x0 + x] = in ? (e_lo + f_lo) * scale : 0.0f;   \
        out[(b1 * S + y) * S + x0 + x] = in ? (e_hi + f_hi) * scale : 0.0f;   \
    }

    STORE_SLOT(aE0, aF0, 0)
    STORE_SLOT(aE1, aF1, 1)
    STORE_SLOT(aE2, aF2, 2)
    STORE_SLOT(aE3, aF3, 3)
#undef STORE_SLOT
}

// ---------------------------------------------------------------------------
extern "C" void kernel_launch(void* const* d_in, const int* in_sizes, int n_in,
                              void* d_out, int out_size) {
    const float* x = (const float*)d_in[0];
    float* out = (float*)d_out;

    filter_kernel<<<NB * NA, 64>>>(x);

    dim3 grid(16, 16, 2);
    backproj_kernel<<<grid, 256>>>(out);
}

// round 5
// speedup vs baseline: 1.5943x; 1.5943x over previous
#include <cuda_runtime.h>
#include <cuda_fp16.h>

#define S    512
#define NA   180
#define NB   4
#define WS   48
#define HALF_A 90
#define PI_D 3.14159265358979323846

// filtered sinogram, batch-pair fp16: [pair][a][s] = uint2 { half2{e0,e1}, half2{d0,d1} }
// e_b = w_b[s] + 0.5*d_b,  d_b = w_b[s+1] - w_b[s]
__device__ uint2 g_xfh[2 * NA * S];

// ---------------------------------------------------------------------------
// Stage 1: ramp filter, register-sliding FIR (one block per (b,a), 64 thr).
// ---------------------------------------------------------------------------
#define OFFM(d) ((d) + ((1 + (d)) >> 3))
#define OFFP(d) ((d) + ((7 + (d)) >> 3))

__global__ void __launch_bounds__(64) filter_kernel(const float* __restrict__ x) {
    const int a = blockIdx.x % NA;
    const int b = blockIdx.x / NA;

    __shared__ float P[1736];
    __shared__ float sg[256];
    __shared__ float sw[S + 8];

    const int t = threadIdx.x;

    #pragma unroll
    for (int i = t; i < 512; i += 64) {
        P[i + (i >> 3)] = 0.0f;
        int j = i + 1024;
        P[j + (j >> 3)] = 0.0f;
    }
    #pragma unroll
    for (int i = t; i < S; i += 64) {
        int ii = i + 512;
        P[ii + (ii >> 3)] = x[(b * S + i) * NA + a];
    }
    #pragma unroll
    for (int i = t; i < 256; i += 64) {
        float dd = (float)(2 * i + 1);
        sg[i] = -2.0f / ((float)(PI_D * PI_D) * dd * dd);
    }
    __syncthreads();

    float acc[8];
    #pragma unroll
    for (int k = 0; k < 8; ++k)
        acc[k] = 0.5f * P[9 * t + 576 + k];

    float Am[16], Ap[16];
    int A0 = 9 * t + 1;
    int A1 = 9 * t + 1132;

    #pragma unroll
    for (int d0 = 0; d0 < 8; ++d0) {
        Am[d0] = P[A0 + OFFM(d0)];
        Ap[d0] = P[A1 + OFFP(16 + d0)];
    }

    #pragma unroll 1
    for (int g = 0; g < 32; ++g) {
        #pragma unroll
        for (int jj = 0; jj < 8; ++jj) {
            float gc = sg[255 - 8 * g - jj];
            #pragma unroll
            for (int k = 0; k < 8; ++k) {
                float av = Am[(2 * jj + k) & 15];
                float bv = Ap[(k - 2 * jj) & 15];
                acc[k] = fmaf(gc, av + bv, acc[k]);
            }
            Am[(2 * jj + 8) & 15]  = P[A0 + OFFM(2 * jj + 8)];
            Am[(2 * jj + 9) & 15]  = P[A0 + OFFM(2 * jj + 9)];
            Ap[(14 - 2 * jj) & 15] = P[A1 + OFFP(14 - 2 * jj)];
            Ap[(15 - 2 * jj) & 15] = P[A1 + OFFP(15 - 2 * jj)];
        }
        A0 += 18;
        A1 -= 18;
    }

    #pragma unroll
    for (int k = 0; k < 8; ++k)
        sw[8 * t + k] = acc[k];
    if (t == 0) sw[S] = 0.0f;
    __syncthreads();

    // write fp16 {e,d} into our batch's 16-bit lanes of the packed pair entry
    __half* ob = (__half*)&g_xfh[((b >> 1) * NA + a) * S];
    const int h = b & 1;
    #pragma unroll
    for (int k = 0; k < 8; ++k) {
        int s = 8 * t + k;
        float lo = sw[s];
        float d  = sw[s + 1] - lo;
        float e  = fmaf(0.5f, d, lo);
        ob[s * 4 + h]     = __float2half(e);
        ob[s * 4 + 2 + h] = __float2half(d);
    }
}

// ---------------------------------------------------------------------------
// Stage 2: backprojection, batch-paired fp16 windows.
// Grid (16,16,2): 32x32 tile x one batch PAIR. 256 threads, 4 y-slots each.
// 2 phases x 90 angles of uint2 fp16 windows (34.5KB) in smem.
// Granular asm: front-end (pure) -> 4 loads -> 4 hfma2+cvt+acc blocks.
// ---------------------------------------------------------------------------
__global__ void __launch_bounds__(256, 4) backproj_kernel(float* __restrict__ out) {
    __shared__ uint2  winh[HALF_A * WS];     // 34560 B
    __shared__ float4 consA[NA];             // {cs, cs, cz, cz}
    __shared__ float4 consB[NA];             // {ns, ns, 8ns, 8ns}
    __shared__ int    w0s[NA];

    const int tid  = threadIdx.x;
    const int pair = blockIdx.z;
    const int x0   = blockIdx.x * 32;
    const int y0   = blockIdx.y * 32;

    const int lane = tid & 31;
    const int w    = tid >> 5;
    const int x    = ((w & 3) << 3) + (lane & 7);        // 0..31
    const int yb   = (lane >> 3) + ((w >> 2) << 2);      // 0..7 (slots +8k)

    const int b0 = 2 * pair, b1 = 2 * pair + 1;
    const float invh = 2.0f / 511.0f;

    // ---- early out: tile fully outside the unit circle ----
    {
        float ux0 = fmaf((float)x0,        invh, -1.0f);
        float ux1 = fmaf((float)(x0 + 31), invh, -1.0f);
        float uy0 = fmaf((float)y0,        invh, -1.0f);
        float uy1 = fmaf((float)(y0 + 31), invh, -1.0f);
        float mx = (ux0 <= 0.0f && ux1 >= 0.0f) ? 0.0f : fminf(fabsf(ux0), fabsf(ux1));
        float my = (uy0 <= 0.0f && uy1 >= 0.0f) ? 0.0f : fminf(fabsf(uy0), fabsf(uy1));
        if (mx * mx + my * my > 1.0f) {
            #pragma unroll
            for (int k = 0; k < 4; ++k) {
                int y = y0 + yb + 8 * k;
                out[(b0 * S + y) * S + x0 + x] = 0.0f;
                out[(b1 * S + y) * S + x0 + x] = 0.0f;
            }
            return;
        }
    }

    // ---- per-angle tables ----
    if (tid < NA) {
        float th = (float)tid * (float)(PI_D / 180.0);
        float sn, cs;
        sincosf(th, &sn, &cs);
        float pb = 255.5f + ((float)x0 - 255.5f) * cs - ((float)y0 - 255.5f) * sn;
        float pmin = pb + fminf(cs * 31.0f, 0.0f) + fminf(-sn * 31.0f, 0.0f);
        int w0 = (int)floorf(pmin) - 1;           // local p in [1, ~46)
        w0s[tid] = w0;
        float cz = pb - (float)w0 - 0.5f;
        float ns = -sn;
        consA[tid] = make_float4(cs, cs, cz, cz);
        consB[tid] = make_float4(ns, ns, 8.0f * ns, 8.0f * ns);
    }
    __syncthreads();

    // ---- packed per-thread constants ----
    unsigned long long FX2, FY2;
    {
        float fx = (float)x, fy = (float)yb;
        asm("mov.b64 %0, {%1, %1};" : "=l"(FX2) : "f"(fx));
        asm("mov.b64 %0, {%1, %1};" : "=l"(FY2) : "f"(fy));
    }
    const unsigned long long MAG2  = 0x4B0000004B000000ull;
    const unsigned long long NMAG2 = 0xCB000000CB000000ull;
    const unsigned long long NONE2 = 0xBF800000BF800000ull;

    // addr = wb + m*8, where m = 0x4B000000 + idx -> fold 0x4B000000*8 mod 2^32
    const unsigned wbase0 = (unsigned)__cvta_generic_to_shared(winh) - 0x58000000u;
    const unsigned cA0 = (unsigned)__cvta_generic_to_shared(consA);
    const unsigned cB0 = (unsigned)__cvta_generic_to_shared(consB);

    unsigned long long acc0 = 0, acc1 = 0, acc2 = 0, acc3 = 0;

    const uint2* __restrict__ gw = &g_xfh[pair * NA * S];

    const int al = (tid < 240) ? tid / WS : 0;     // 0..4
    const int oo = tid - al * WS;

    #pragma unroll 1
    for (int phase = 0; phase < 2; ++phase) {
        const int abase = phase * HALF_A;

        // ---- cooperative window fill (straight uint2 copy) ----
        if (tid < 240) {
            #pragma unroll
            for (int ar = al; ar < HALF_A; ar += 5) {
                int a  = abase + ar;
                int gi = w0s[a] + oo;
                uint2 v;
                if ((unsigned)gi < (unsigned)S) {
                    v = gw[a * S + gi];
                } else if (gi == -1) {
                    uint2 v0 = gw[a * S];
                    __half2 e2 = *(__half2*)&v0.x;
                    __half2 d2 = *(__half2*)&v0.y;
                    float w00 = __low2float(e2)  - 0.5f * __low2float(d2);
                    float w01 = __high2float(e2) - 0.5f * __high2float(d2);
                    __half2 ne = __floats2half2_rn(0.5f * w00, 0.5f * w01);
                    __half2 nd = __floats2half2_rn(w00, w01);
                    v.x = *(unsigned*)&ne;
                    v.y = *(unsigned*)&nd;
                } else {
                    v.x = 0u; v.y = 0u;
                }
                winh[ar * WS + oo] = v;
            }
        }
        __syncthreads();

        unsigned caA = cA0 + (unsigned)abase * 16u;
        unsigned caB = cB0 + (unsigned)abase * 16u;
        unsigned wb  = wbase0;

        #pragma unroll 2
        for (int a = 0; a < HALF_A; ++a) {
            unsigned m0, m1, m2, m3, f0, f1, f2, f3;
            // ---- front-end: addresses + fr(half2) for 4 slots (pure math) ----
            asm("{\n\t"
                ".reg .b64 XCS, XCZ, XNS, XN8, BX, TP0, TP1, TP2, TP3, TPM, TFL, TQ;\n\t"
                ".reg .f32 ql, qh;\n\t"
                ".reg .b32 mt;\n\t"
                "ld.shared.v2.b64 {XCS, XCZ}, [%8];\n\t"
                "ld.shared.v2.b64 {XNS, XN8}, [%9];\n\t"
                "fma.rn.f32x2 BX, XCS, %10, XCZ;\n\t"
                "fma.rn.f32x2 TP0, XNS, %11, BX;\n\t"
                "add.rn.f32x2 TP1, TP0, XN8;\n\t"
                "add.rn.f32x2 TP2, TP1, XN8;\n\t"
                "add.rn.f32x2 TP3, TP2, XN8;\n\t"

                "add.rn.f32x2 TPM, TP0, %12;\n\t"
                "mov.b64 {%0, mt}, TPM;\n\t"
                "add.rn.f32x2 TFL, TPM, %13;\n\t"
                "fma.rn.f32x2 TQ, TFL, %14, TP0;\n\t"
                "mov.b64 {ql, qh}, TQ;\n\t"
                "cvt.rn.f16x2.f32 %4, ql, ql;\n\t"
                "mad.lo.u32 %0, %0, 8, %15;\n\t"

                "add.rn.f32x2 TPM, TP1, %12;\n\t"
                "mov.b64 {%1, mt}, TPM;\n\t"
                "add.rn.f32x2 TFL, TPM, %13;\n\t"
                "fma.rn.f32x2 TQ, TFL, %14, TP1;\n\t"
                "mov.b64 {ql, qh}, TQ;\n\t"
                "cvt.rn.f16x2.f32 %5, ql, ql;\n\t"
                "mad.lo.u32 %1, %1, 8, %15;\n\t"

                "add.rn.f32x2 TPM, TP2, %12;\n\t"
                "mov.b64 {%2, mt}, TPM;\n\t"
                "add.rn.f32x2 TFL, TPM, %13;\n\t"
                "fma.rn.f32x2 TQ, TFL, %14, TP2;\n\t"
                "mov.b64 {ql, qh}, TQ;\n\t"
                "cvt.rn.f16x2.f32 %6, ql, ql;\n\t"
                "mad.lo.u32 %2, %2, 8, %15;\n\t"

                "add.rn.f32x2 TPM, TP3, %12;\n\t"
                "mov.b64 {%3, mt}, TPM;\n\t"
                "add.rn.f32x2 TFL, TPM, %13;\n\t"
                "fma.rn.f32x2 TQ, TFL, %14, TP3;\n\t"
                "mov.b64 {ql, qh}, TQ;\n\t"
                "cvt.rn.f16x2.f32 %7, ql, ql;\n\t"
                "mad.lo.u32 %3, %3, 8, %15;\n\t"
                "}"
                : "=r"(m0), "=r"(m1), "=r"(m2), "=r"(m3),
                  "=r"(f0), "=r"(f1), "=r"(f2), "=r"(f3)
                : "r"(caA), "r"(caB), "l"(FX2), "l"(FY2),
                  "l"(MAG2), "l"(NMAG2), "l"(NONE2), "r"(wb)
                : "memory");

            // ---- 4 loads issued back-to-back (latency overlapped) ----
            unsigned E0, D0, E1, D1, E2, D2, E3, D3;
            asm volatile("ld.shared.v2.b32 {%0, %1}, [%2];" : "=r"(E0), "=r"(D0) : "r"(m0));
            asm volatile("ld.shared.v2.b32 {%0, %1}, [%2];" : "=r"(E1), "=r"(D1) : "r"(m1));
            asm volatile("ld.shared.v2.b32 {%0, %1}, [%2];" : "=r"(E2), "=r"(D2) : "r"(m2));
            asm volatile("ld.shared.v2.b32 {%0, %1}, [%2];" : "=r"(E3), "=r"(D3) : "r"(m3));

            // ---- interpolate (half2) + accumulate (f32x2) ----
#define SLOT_ACC(FRH, EE, DD, ACC)                                            \
            asm("{\n\t"                                                       \
                ".reg .b32 tt;\n\t"                                           \
                ".reg .b16 hl, hh;\n\t"                                       \
                ".reg .f32 fl2, fh2;\n\t"                                     \
                ".reg .b64 t2;\n\t"                                           \
                "fma.rn.f16x2 tt, %1, %2, %3;\n\t"                            \
                "mov.b32 {hl, hh}, tt;\n\t"                                   \
                "cvt.f32.f16 fl2, hl;\n\t"                                    \
                "cvt.f32.f16 fh2, hh;\n\t"                                    \
                "mov.b64 t2, {fl2, fh2};\n\t"                                 \
                "add.rn.f32x2 %0, %0, t2;\n\t"                                \
                "}"                                                           \
                : "+l"(ACC) : "r"(FRH), "r"(DD), "r"(EE));

            SLOT_ACC(f0, E0, D0, acc0)
            SLOT_ACC(f1, E1, D1, acc1)
            SLOT_ACC(f2, E2, D2, acc2)
            SLOT_ACC(f3, E3, D3, acc3)
#undef SLOT_ACC

            caA += 16u;
            caB += 16u;
            wb  += (unsigned)(WS * 8);
        }
        __syncthreads();
    }

    // ---- unpack, mask, scale, store (both batches) ----
    const float scale = (float)(PI_D / (2.0 * NA));
    const float ux  = fmaf((float)(x0 + x), invh, -1.0f);
    const float uxx = ux * ux;

#define STORE_SLOT(ACC, K)                                                    \
    {                                                                         \
        float s_lo, s_hi;                                                     \
        asm("mov.b64 {%0, %1}, %2;" : "=f"(s_lo), "=f"(s_hi) : "l"(ACC));     \
        int y = y0 + yb + 8 * (K);                                            \
        float uy = fmaf((float)y, invh, -1.0f);                               \
        bool in = (uxx + uy * uy <= 1.0f);                                    \
        out[(b0 * S + y) * S + x0 + x] = in ? s_lo * scale : 0.0f;            \
        out[(b1 * S + y) * S + x0 + x] = in ? s_hi * scale : 0.0f;            \
    }

    STORE_SLOT(acc0, 0)
    STORE_SLOT(acc1, 1)
    STORE_SLOT(acc2, 2)
    STORE_SLOT(acc3, 3)
#undef STORE_SLOT
}

// ---------------------------------------------------------------------------
extern "C" void kernel_launch(void* const* d_in, const int* in_sizes, int n_in,
                              void* d_out, int out_size) {
    const float* x = (const float*)d_in[0];
    float* out = (float*)d_out;

    filter_kernel<<<NB * NA, 64>>>(x);

    dim3 grid(16, 16, 2);
    backproj_kernel<<<grid, 256>>>(out);
}